// round 11
// baseline (speedup 1.0000x reference)
#include <cuda_runtime.h>
#include <cstddef>
#include <cstdint>

#define BATCH 32
#define NUU   64
#define NYY   64
#define NXX   512
#define NWW   512
#define TSTEP 1024
#define CLS   16      // CTAs per cluster
#define NCLU  8       // clusters (8 x 16 = 128 CTAs)
#define CB    4       // batches per cluster
#define CROWS 32      // rows per CTA

typedef unsigned long long u64;

// ---------------- packed f32x2 helpers ----------------------------------------
#define FMA2(acc, w, h) asm("fma.rn.f32x2 %0, %1, %2, %0;" : "+l"(acc) : "l"(w), "l"(h))
#define ADD2(acc, v)    asm("add.rn.f32x2 %0, %0, %1;"     : "+l"(acc) : "l"(v))
__device__ __forceinline__ u64 dup2(float a) {
    u64 r;
    asm("mov.b64 %0, {%1, %1};" : "=l"(r) : "r"(__float_as_uint(a)));
    return r;
}

// ---------------- device scratch ----------------------------------------------
__device__ float d_Cv[NWW * NXX];
__device__ float d_Dv[NWW * NUU];
__device__ float d_X[NXX * NXX];
__device__ float d_X2[NXX * NXX];
__device__ float d_T1[NXX * NXX];
__device__ float d_Ahat[NXX * NXX];
__device__ float d_Bhat[NXX * NWW];
__device__ float d_B2hat[NXX * NUU];
__device__ float d_fbhat[NXX];
__device__ float d_G1[(size_t)TSTEP * BATCH * NWW];     // [t][b][j]
__device__ float d_G2[(size_t)TSTEP * BATCH * NXX];     // [t][b][x]
__device__ float d_states[(size_t)TSTEP * BATCH * NXX]; // [t][b][x]
__device__ float d_Wb[(size_t)TSTEP * BATCH * NWW];     // [t][b][j]
__device__ unsigned g_pcnt;                             // prep-gemm grid barrier

// ---------------- sync primitives (prep chain) ---------------------------------
__device__ __forceinline__ void rel_add1(unsigned* cnt) {
    asm volatile("red.release.gpu.add.u32 [%0], 1;" :: "l"(cnt) : "memory");
}
__device__ __forceinline__ void wait_cnt(unsigned* cnt, unsigned target) {
    unsigned v;
    do {
        asm volatile("ld.acquire.gpu.u32 %0, [%1];" : "=r"(v) : "l"(cnt) : "memory");
    } while (v < target);
}

// ---------------- cluster / mbarrier primitives --------------------------------
__device__ __forceinline__ uint32_t smem_u32(const void* p) {
    uint32_t a;
    asm("{ .reg .u64 t; cvta.to.shared.u64 t, %1; cvt.u32.u64 %0, t; }" : "=r"(a) : "l"(p));
    return a;
}
__device__ __forceinline__ uint32_t ctarank() {
    uint32_t r;
    asm("mov.u32 %0, %%cluster_ctarank;" : "=r"(r));
    return r;
}
#define MBAR_INIT(addr, cnt) \
    asm volatile("mbarrier.init.shared.b64 [%0], %1;" :: "r"(addr), "r"(cnt) : "memory")
#define CLUSTER_SYNC() do { \
    asm volatile("barrier.cluster.arrive.aligned;" ::: "memory"); \
    asm volatile("barrier.cluster.wait.aligned;" ::: "memory"); \
} while (0)
// store float4 into peer CTA's smem at same local offset
#define ST_PEER_V4(laddr, peer, v) \
    asm volatile("{ .reg .b32 ra; mapa.shared::cluster.u32 ra, %0, %1;\n\t" \
                 "st.shared::cluster.v4.f32 [ra], {%2, %3, %4, %5}; }" \
                 :: "r"(laddr), "r"(peer), "f"((v).x), "f"((v).y), "f"((v).z), "f"((v).w) : "memory")
// release-arrive (cluster scope) on peer CTA's mbarrier
#define MBAR_ARRIVE_PEER(laddr, peer) \
    asm volatile("{ .reg .b32 ra; mapa.shared::cluster.u32 ra, %0, %1;\n\t" \
                 "mbarrier.arrive.release.cluster.shared::cluster.b64 _, [ra]; }" \
                 :: "r"(laddr), "r"(peer) : "memory")
// acquire-wait: NON-SLEEPING test_wait poll (the R9/R10 try_wait with a 10ms
// suspend hint parked threads for a multi-microsecond quantum per wait)
__device__ __forceinline__ void mbar_wait(uint32_t addr, uint32_t parity) {
    uint32_t done;
    do {
        asm volatile("{\n\t"
                     ".reg .pred P;\n\t"
                     "mbarrier.test_wait.parity.acquire.cluster.shared::cta.b64 P, [%1], %2;\n\t"
                     "selp.b32 %0, 1, 0, P;\n\t"
                     "}" : "=r"(done) : "r"(addr), "r"(parity) : "memory");
    } while (!done);
}

// ---------------- prep: Cv, Dv, X0 = 2I - E, reset prep barrier ---------------
__global__ void prep_kernel(const float* __restrict__ C2, const float* __restrict__ mult,
                            const float* __restrict__ Dt, const float* __restrict__ E) {
    int i = blockIdx.x * blockDim.x + threadIdx.x;
    int stride = gridDim.x * blockDim.x;
    if (i == 0) g_pcnt = 0u;
    for (int idx = i; idx < NWW * NXX; idx += stride) {
        int r = idx / NXX;
        d_Cv[idx] = C2[idx] / mult[r];
    }
    for (int idx = i; idx < NWW * NUU; idx += stride) {
        int r = idx / NUU;
        d_Dv[idx] = Dt[idx] / mult[r];
    }
    for (int idx = i; idx < NXX * NXX; idx += stride) {
        int r = idx / NXX, c = idx % NXX;
        d_X[idx] = (r == c ? 2.0f : 0.0f) - E[idx];
    }
}

// ---------------- fused prep GEMM chain (persistent, 64 CTAs) -----------------
__device__ __forceinline__ void gemm_tile(const float* __restrict__ A, const float* __restrict__ Bm,
                                          float* __restrict__ C, int N, int K, int mode,
                                          int bx, int by,
                                          float (*As)[16][64], float (*Bs)[16][64]) {
    int tid = threadIdx.x;
    int tx = tid & 15, ty = tid >> 4;
    int ar = tid >> 2, ac = (tid & 3) << 2;
    int br = tid >> 4, bc = (tid & 15) << 2;
    const float* Aptr = A + (size_t)(by * 64 + ar) * K + ac;
    const float* Bptr = Bm + (size_t)br * N + bx * 64 + bc;

    float4 av = *(const float4*)Aptr;
    float4 bv = *(const float4*)Bptr;
    As[0][ac + 0][ar] = av.x; As[0][ac + 1][ar] = av.y;
    As[0][ac + 2][ar] = av.z; As[0][ac + 3][ar] = av.w;
    *(float4*)&Bs[0][br][bc] = bv;
    __syncthreads();

    float acc[4][4] = {};
    int buf = 0;
    for (int k0 = 16; k0 <= K; k0 += 16) {
        if (k0 < K) {
            av = *(const float4*)(Aptr + k0);
            bv = *(const float4*)(Bptr + (size_t)k0 * N);
        }
#pragma unroll
        for (int k = 0; k < 16; k++) {
            float4 a = *(const float4*)&As[buf][k][ty * 4];
            float4 b = *(const float4*)&Bs[buf][k][tx * 4];
            acc[0][0] = fmaf(a.x, b.x, acc[0][0]); acc[0][1] = fmaf(a.x, b.y, acc[0][1]);
            acc[0][2] = fmaf(a.x, b.z, acc[0][2]); acc[0][3] = fmaf(a.x, b.w, acc[0][3]);
            acc[1][0] = fmaf(a.y, b.x, acc[1][0]); acc[1][1] = fmaf(a.y, b.y, acc[1][1]);
            acc[1][2] = fmaf(a.y, b.z, acc[1][2]); acc[1][3] = fmaf(a.y, b.w, acc[1][3]);
            acc[2][0] = fmaf(a.z, b.x, acc[2][0]); acc[2][1] = fmaf(a.z, b.y, acc[2][1]);
            acc[2][2] = fmaf(a.z, b.z, acc[2][2]); acc[2][3] = fmaf(a.z, b.w, acc[2][3]);
            acc[3][0] = fmaf(a.w, b.x, acc[3][0]); acc[3][1] = fmaf(a.w, b.y, acc[3][1]);
            acc[3][2] = fmaf(a.w, b.z, acc[3][2]); acc[3][3] = fmaf(a.w, b.w, acc[3][3]);
        }
        if (k0 < K) {
            int nb = buf ^ 1;
            As[nb][ac + 0][ar] = av.x; As[nb][ac + 1][ar] = av.y;
            As[nb][ac + 2][ar] = av.z; As[nb][ac + 3][ar] = av.w;
            *(float4*)&Bs[nb][br][bc] = bv;
        }
        __syncthreads();
        buf ^= 1;
    }
#pragma unroll
    for (int i = 0; i < 4; i++) {
        int r = by * 64 + ty * 4 + i;
        float o[4];
#pragma unroll
        for (int j = 0; j < 4; j++) {
            int cx = bx * 64 + tx * 4 + j;
            float v = acc[i][j];
            if (mode) v = (r == cx ? 2.0f : 0.0f) - v;
            o[j] = v;
        }
        *(float4*)&C[(size_t)r * N + bx * 64 + tx * 4] = make_float4(o[0], o[1], o[2], o[3]);
    }
}

__device__ __forceinline__ void gbar(unsigned gen) {
    __threadfence();
    __syncthreads();
    if (threadIdx.x == 0) {
        rel_add1(&g_pcnt);
        wait_cnt(&g_pcnt, 64u * gen);
    }
    __syncthreads();
}

__global__ void __launch_bounds__(256, 1) prepgemm_kernel(
        const float* __restrict__ E, const float* __restrict__ F_w,
        const float* __restrict__ F_b, const float* __restrict__ B1_w,
        const float* __restrict__ B2_w) {
    __shared__ float As[2][16][64];
    __shared__ float Bs[2][16][64];
    int cta = blockIdx.x;
    int bx = cta & 7, by = cta >> 3;

    // Newton-Schulz: 3 iterations, X0 in d_X
    gemm_tile(E, d_X, d_T1, 512, 512, 1, bx, by, As, Bs);  gbar(1);
    gemm_tile(d_X, d_T1, d_X2, 512, 512, 0, bx, by, As, Bs); gbar(2);
    gemm_tile(E, d_X2, d_T1, 512, 512, 1, bx, by, As, Bs); gbar(3);
    gemm_tile(d_X2, d_T1, d_X, 512, 512, 0, bx, by, As, Bs); gbar(4);
    gemm_tile(E, d_X, d_T1, 512, 512, 1, bx, by, As, Bs);  gbar(5);
    gemm_tile(d_X, d_T1, d_X2, 512, 512, 0, bx, by, As, Bs); gbar(6);
    // d_X2 = Einv
    gemm_tile(d_X2, F_w, d_Ahat, 512, 512, 0, bx, by, As, Bs);
    gemm_tile(d_X2, B1_w, d_Bhat, 512, 512, 0, bx, by, As, Bs);
    if (cta < 8) {
        gemm_tile(d_X2, B2_w, d_B2hat, 64, 512, 0, 0, cta, As, Bs);
    } else if (cta < 16 && threadIdx.x < 64) {
        int r = (cta - 8) * 64 + threadIdx.x;
        float s = 0.f;
        for (int k = 0; k < NXX; k++) s = fmaf(d_X2[(size_t)r * NXX + k], F_b[k], s);
        d_fbhat[r] = s;
    }
}

// ---------------- u projections: out[(t*B + b)*J + j] -------------------------
__global__ void uproj_kernel(const float* __restrict__ u, const float* __restrict__ M,
                             const float* __restrict__ bias, float* __restrict__ out, int J) {
    __shared__ float U_s[NUU][65];
    __shared__ float M_s[64][65];
    int tid = threadIdx.x;
    int j0 = blockIdx.x * 64, t0 = blockIdx.y * 64, b = blockIdx.z;
    for (int i = tid; i < 64 * 64; i += 256) {
        int kk = i >> 6, tt = i & 63;
        U_s[kk][tt] = u[(size_t)b * NUU * TSTEP + (size_t)kk * TSTEP + t0 + tt];
    }
    for (int i = tid; i < 64 * 64; i += 256) {
        int j = i >> 6, k = i & 63;
        M_s[j][k] = M[(size_t)(j0 + j) * NUU + k];
    }
    __syncthreads();
    int lane = tid & 31, wg = tid >> 5;
    float acc0[8] = {}, acc1[8] = {};
    for (int k = 0; k < 64; k++) {
        float u0 = U_s[k][lane], u1 = U_s[k][lane + 32];
#pragma unroll
        for (int j = 0; j < 8; j++) {
            float m = M_s[wg * 8 + j][k];
            acc0[j] = fmaf(u0, m, acc0[j]);
            acc1[j] = fmaf(u1, m, acc1[j]);
        }
    }
    int jj0 = j0 + wg * 8;
    float bsv[8];
#pragma unroll
    for (int j = 0; j < 8; j++) bsv[j] = bias[jj0 + j];
    size_t r0 = ((size_t)(t0 + lane) * BATCH + b) * J + jj0;
    size_t r1 = ((size_t)(t0 + lane + 32) * BATCH + b) * J + jj0;
    *(float4*)&out[r0]     = make_float4(acc0[0] + bsv[0], acc0[1] + bsv[1], acc0[2] + bsv[2], acc0[3] + bsv[3]);
    *(float4*)&out[r0 + 4] = make_float4(acc0[4] + bsv[4], acc0[5] + bsv[5], acc0[6] + bsv[6], acc0[7] + bsv[7]);
    *(float4*)&out[r1]     = make_float4(acc1[0] + bsv[0], acc1[1] + bsv[1], acc1[2] + bsv[2], acc1[3] + bsv[3]);
    *(float4*)&out[r1 + 4] = make_float4(acc1[4] + bsv[4], acc1[5] + bsv[5], acc1[6] + bsv[6], acc1[7] + bsv[7]);
}

// ---------------- persistent cluster recurrence --------------------------------
// 8 clusters x 16 CTAs. Cluster c: batches [4c, 4c+4). CTA rank r: rows [32r, 32r+32).
// State exchange: DSMEM pushes; one release-arrive per peer per phase (count=15).
#define SM_WCV  0
#define SM_WAB  16384
#define SM_H0   49152
#define SM_H1   51200
#define SM_WS   53248
#define SM_PB   55296
#define SM_FLOATS 56416
#define SMEM_RECUR (SM_FLOATS * 4 + 16)

__global__ void __launch_bounds__(256, 1) recur_kernel() {
    extern __shared__ float sm[];
    float* wCv  = sm + SM_WCV;   // [k][32 rows]
    float* wAB  = sm + SM_WAB;   // [k(1024)][32 rows]
    float* w_s  = sm + SM_WS;    // [j][4 b]
    float* pbuf = sm + SM_PB;    // [8 warps][140]
    uint32_t smb = smem_u32(sm);
    uint32_t mb_w = smb + SM_FLOATS * 4;
    uint32_t mb_h = mb_w + 8;

    int tid = threadIdx.x;
    uint32_t rank = ctarank();
    int cid = blockIdx.x >> 4;
    int j0 = (int)rank * CROWS;
    int warp = tid >> 5, lane = tid & 31;
    int kh = lane & 3, rh = (lane >> 2) & 1, bq = lane >> 3;
    int rrow = tid & 31, rb = tid >> 5;          // reduce mapping (tid<128)
    int bglob = cid * CB + rb;

    // stage weight slices
    for (int i = tid; i < CROWS * NXX; i += 256) {
        int c = i >> 9, k = i & 511;
        wCv[k * 32 + c] = d_Cv[(size_t)(j0 + c) * NXX + k];
    }
    for (int i = tid; i < CROWS * 1024; i += 256) {
        int c = i >> 10, k = i & 1023;
        wAB[k * 32 + c] = (k < NXX) ? d_Ahat[(size_t)(j0 + c) * NXX + k]
                                    : d_Bhat[(size_t)(j0 + c) * NWW + (k - NXX)];
    }
    // zero h0 (full), store states t=0
    for (int i = tid; i < NXX * CB; i += 256) sm[SM_H0 + i] = 0.f;
    if (tid < 128)
        d_states[(size_t)bglob * NXX + j0 + rrow] = 0.f;
    if (tid == 0) {
        MBAR_INIT(mb_w, 15);
        MBAR_INIT(mb_h, 15);
    }
    __syncthreads();
    CLUSTER_SYNC();   // mbarriers + buffers visible cluster-wide

    // broadcast crew: 240 threads, 16 per peer (one half-warp), 2 float4 chunks each
    int pi = tid >> 4;
    int peer = pi + (pi >= (int)rank ? 1 : 0);
    int ch = (tid & 15) * 2;
    bool is_crew = (tid < 240);
    bool is_lead = is_crew && ((tid & 15) == 0);

    for (int t = 0; t < TSTEP; t++) {
        float g1 = 0.f, g2 = 0.f;
        if (tid < 128) {
            g1 = __ldcg(&d_G1[((size_t)t * BATCH + bglob) * NWW + j0 + rrow]);
            if (t < TSTEP - 1)
                g2 = __ldcg(&d_G2[((size_t)t * BATCH + bglob) * NXX + j0 + rrow]);
        }
        // wait for h(t) pushes (prefetch LDGs already in flight)
        if (t > 0) mbar_wait(mb_h, (uint32_t)((t - 1) & 1));
        const float* hsrc = sm + ((t & 1) ? SM_H1 : SM_H0);

        // ---- phase A: Cv @ h ----
        {
            u64 acc[8] = {};
            int kb = warp * 64 + kh;
#pragma unroll
            for (int i = 0; i < 16; i++) {
                int k = kb + 4 * i;
                u64 h2 = dup2(hsrc[k * 4 + bq]);
                const float* wr = wCv + k * 32 + rh * 16;
#pragma unroll
                for (int j = 0; j < 4; j++) {
                    int sl = (j + kh) & 3;
                    ulonglong2 wv = *(const ulonglong2*)(wr + sl * 4);
                    FMA2(acc[2 * sl], wv.x, h2);
                    FMA2(acc[2 * sl + 1], wv.y, h2);
                }
            }
#pragma unroll
            for (int m = 1; m <= 2; m <<= 1)
#pragma unroll
                for (int p = 0; p < 8; p++) {
                    u64 o = __shfl_xor_sync(0xffffffffu, acc[p], m);
                    ADD2(acc[p], o);
                }
            if (kh == 0) {
                u64* pb = (u64*)(pbuf + warp * 140 + bq * 34 + rh * 16);
#pragma unroll
                for (int p = 0; p < 8; p++) pb[p] = acc[p];
            }
        }
        __syncthreads();  // S1
        if (tid < 128) {
            float v = g1;
#pragma unroll
            for (int w8 = 0; w8 < 8; w8++) v += pbuf[w8 * 140 + rb * 34 + rrow];
            v = fmaxf(v, 0.f);
            w_s[(j0 + rrow) * 4 + rb] = v;
            d_Wb[((size_t)t * BATCH + bglob) * NWW + j0 + rrow] = v;
        }
        if (t == TSTEP - 1) break;
        __syncthreads();  // S2
        // ---- push w slice to 15 peers; one arrive per peer ----
        if (is_crew) {
            float4 v0 = ((const float4*)w_s)[j0 + ch];
            float4 v1 = ((const float4*)w_s)[j0 + ch + 1];
            uint32_t a0 = smb + SM_WS * 4 + (j0 + ch) * 16;
            ST_PEER_V4(a0, peer, v0);
            ST_PEER_V4(a0 + 16, peer, v1);
        }
        __syncwarp();
        if (is_lead) MBAR_ARRIVE_PEER(mb_w, peer);
        // ---- phase B: [Ahat|Bhat] @ [h; w] ----
        {
            if (warp >= 4) mbar_wait(mb_w, (uint32_t)(t & 1));
            const float* srcB = (warp < 4) ? hsrc : (w_s - NXX * 4);
            u64 acc[8] = {};
            int kb = warp * 128 + kh;
#pragma unroll
            for (int i = 0; i < 32; i++) {
                int k = kb + 4 * i;
                u64 h2 = dup2(srcB[k * 4 + bq]);
                const float* wr = wAB + k * 32 + rh * 16;
#pragma unroll
                for (int j = 0; j < 4; j++) {
                    int sl = (j + kh) & 3;
                    ulonglong2 wv = *(const ulonglong2*)(wr + sl * 4);
                    FMA2(acc[2 * sl], wv.x, h2);
                    FMA2(acc[2 * sl + 1], wv.y, h2);
                }
            }
#pragma unroll
            for (int m = 1; m <= 2; m <<= 1)
#pragma unroll
                for (int p = 0; p < 8; p++) {
                    u64 o = __shfl_xor_sync(0xffffffffu, acc[p], m);
                    ADD2(acc[p], o);
                }
            if (kh == 0) {
                u64* pb = (u64*)(pbuf + warp * 140 + bq * 34 + rh * 16);
#pragma unroll
                for (int p = 0; p < 8; p++) pb[p] = acc[p];
            }
        }
        __syncthreads();  // S3
        int hn_off = ((t & 1) ? SM_H0 : SM_H1);
        if (tid < 128) {
            float v = g2;
#pragma unroll
            for (int w8 = 0; w8 < 8; w8++) v += pbuf[w8 * 140 + rb * 34 + rrow];
            sm[hn_off + (j0 + rrow) * 4 + rb] = v;
            d_states[((size_t)(t + 1) * BATCH + bglob) * NXX + j0 + rrow] = v;
        }
        __syncthreads();  // S4
        // ---- push h(t+1) slice to 15 peers; one arrive per peer ----
        if (is_crew) {
            const float4* hb = (const float4*)(sm + hn_off);
            float4 v0 = hb[j0 + ch];
            float4 v1 = hb[j0 + ch + 1];
            uint32_t a0 = smb + hn_off * 4 + (j0 + ch) * 16;
            ST_PEER_V4(a0, peer, v0);
            ST_PEER_V4(a0 + 16, peer, v1);
        }
        __syncwarp();
        if (is_lead) MBAR_ARRIVE_PEER(mb_h, peer);
    }
    CLUSTER_SYNC();
}

// ---------------- epilogue: y = states@C1.T + W@D11.T + u@D12.T + by ----------
__global__ void yfinal_kernel(const float* __restrict__ u, const float* __restrict__ C1,
                              const float* __restrict__ D11, const float* __restrict__ D12,
                              const float* __restrict__ by, float* __restrict__ out) {
    __shared__ float As[64][65];
    __shared__ float Bs[64][68];
    int tid = threadIdx.x;
    int tx = tid & 15, ty = tid >> 4;
    int t0 = blockIdx.x * 64, b = blockIdx.y;
    float acc[4][4] = {};
    for (int seg = 0; seg < 3; seg++) {
        int nchunk = (seg == 2) ? 1 : 8;
        const float* Am = (seg == 0) ? C1 : (seg == 1) ? D11 : D12;
        int Ksz = (seg == 2) ? 64 : 512;
        for (int ch = 0; ch < nchunk; ch++) {
            int x0 = ch * 64;
            for (int i = tid; i < 64 * 64; i += 256) {
                int j = i >> 6, k = i & 63;
                As[j][k] = Am[(size_t)j * Ksz + x0 + k];
            }
            if (seg == 2) {
                for (int i = tid; i < 64 * 64; i += 256) {
                    int k = i >> 6, tt = i & 63;
                    Bs[k][tt] = u[((size_t)b * NUU + k) * TSTEP + t0 + tt];
                }
            } else {
                const float* S = (seg == 0) ? d_states : d_Wb;
                for (int i = tid; i < 64 * 64; i += 256) {
                    int tt = i >> 6, xx = i & 63;
                    Bs[xx][tt] = S[((size_t)(t0 + tt) * BATCH + b) * 512 + x0 + xx];
                }
            }
            __syncthreads();
#pragma unroll 8
            for (int k = 0; k < 64; k++) {
                float a0 = As[ty * 4 + 0][k];
                float a1 = As[ty * 4 + 1][k];
                float a2 = As[ty * 4 + 2][k];
                float a3 = As[ty * 4 + 3][k];
                float4 bv = *(const float4*)&Bs[k][tx * 4];
                acc[0][0] = fmaf(a0, bv.x, acc[0][0]); acc[0][1] = fmaf(a0, bv.y, acc[0][1]);
                acc[0][2] = fmaf(a0, bv.z, acc[0][2]); acc[0][3] = fmaf(a0, bv.w, acc[0][3]);
                acc[1][0] = fmaf(a1, bv.x, acc[1][0]); acc[1][1] = fmaf(a1, bv.y, acc[1][1]);
                acc[1][2] = fmaf(a1, bv.z, acc[1][2]); acc[1][3] = fmaf(a1, bv.w, acc[1][3]);
                acc[2][0] = fmaf(a2, bv.x, acc[2][0]); acc[2][1] = fmaf(a2, bv.y, acc[2][1]);
                acc[2][2] = fmaf(a2, bv.z, acc[2][2]); acc[2][3] = fmaf(a2, bv.w, acc[2][3]);
                acc[3][0] = fmaf(a3, bv.x, acc[3][0]); acc[3][1] = fmaf(a3, bv.y, acc[3][1]);
                acc[3][2] = fmaf(a3, bv.z, acc[3][2]); acc[3][3] = fmaf(a3, bv.w, acc[3][3]);
            }
            __syncthreads();
        }
    }
#pragma unroll
    for (int i = 0; i < 4; i++) {
        int j = ty * 4 + i;
        float bj = by[j];
        float4 o = make_float4(acc[i][0] + bj, acc[i][1] + bj, acc[i][2] + bj, acc[i][3] + bj);
        *(float4*)&out[((size_t)b * NYY + j) * TSTEP + t0 + tx * 4] = o;
    }
}

// ---------------- launch ------------------------------------------------------
extern "C" void kernel_launch(void* const* d_in, const int* in_sizes, int n_in,
                              void* d_out, int out_size) {
    const float* u      = (const float*)d_in[0];
    const float* E      = (const float*)d_in[1];
    const float* F_w    = (const float*)d_in[2];
    const float* F_b    = (const float*)d_in[3];
    const float* B1_w   = (const float*)d_in[4];
    const float* B2_w   = (const float*)d_in[5];
    const float* C2tild = (const float*)d_in[6];
    const float* bv     = (const float*)d_in[7];
    const float* Dtild  = (const float*)d_in[8];
    const float* C1_w   = (const float*)d_in[9];
    const float* D11_w  = (const float*)d_in[10];
    const float* D12_w  = (const float*)d_in[11];
    const float* by     = (const float*)d_in[12];
    const float* multis = (const float*)d_in[13];
    float* out = (float*)d_out;

    float *Dv, *G1, *G2, *B2hat, *fbhat;
    cudaGetSymbolAddress((void**)&Dv,    d_Dv);
    cudaGetSymbolAddress((void**)&G1,    d_G1);
    cudaGetSymbolAddress((void**)&G2,    d_G2);
    cudaGetSymbolAddress((void**)&B2hat, d_B2hat);
    cudaGetSymbolAddress((void**)&fbhat, d_fbhat);

    cudaFuncSetAttribute(recur_kernel, cudaFuncAttributeNonPortableClusterSizeAllowed, 1);
    cudaFuncSetAttribute(recur_kernel, cudaFuncAttributeMaxDynamicSharedMemorySize, SMEM_RECUR);

    // 1) Cv, Dv, X0 = 2I - E, reset prep barrier
    prep_kernel<<<256, 256>>>(C2tild, multis, Dtild, E);
    // 2) fused Newton-Schulz (3 iters) + weight folding
    prepgemm_kernel<<<64, 256>>>(E, F_w, F_b, B1_w, B2_w);
    // 3,4) input-driven terms
    uproj_kernel<<<dim3(8, 16, 32), 256>>>(u, Dv, bv, G1, NWW);
    uproj_kernel<<<dim3(8, 16, 32), 256>>>(u, B2hat, fbhat, G2, NXX);
    // 5) cluster recurrence (8 clusters x 16 CTAs, DSMEM push, test_wait polling)
    {
        cudaLaunchConfig_t cfg = {};
        cfg.gridDim = dim3(NCLU * CLS, 1, 1);
        cfg.blockDim = dim3(256, 1, 1);
        cfg.dynamicSmemBytes = SMEM_RECUR;
        cudaLaunchAttribute attrs[1];
        attrs[0].id = cudaLaunchAttributeClusterDimension;
        attrs[0].val.clusterDim.x = CLS;
        attrs[0].val.clusterDim.y = 1;
        attrs[0].val.clusterDim.z = 1;
        cfg.attrs = attrs;
        cfg.numAttrs = 1;
        cudaLaunchKernelEx(&cfg, recur_kernel);
    }
    // 6) epilogue
    yfinal_kernel<<<dim3(16, 32), 256>>>(u, C1_w, D11_w, D12_w, by, out);
}

// round 14
// speedup vs baseline: 14.5219x; 14.5219x over previous
#include <cuda_runtime.h>
#include <cstddef>
#include <cstdint>

#define BATCH 32
#define NUU   64
#define NYY   64
#define NXX   512
#define NWW   512
#define TSTEP 1024
#define RCTAS 128
#define RTHR  256
#define GROUPS 4
#define GCTAS 32     // CTAs per group
#define BGS   8      // batches per group
#define ROWS  16     // rows per CTA
#define PST   136    // partial-buffer stride (floats)

typedef unsigned long long u64;

// ---------------- packed f32x2 helpers ----------------------------------------
#define FMA2(acc, w, h) asm("fma.rn.f32x2 %0, %1, %2, %0;" : "+l"(acc) : "l"(w), "l"(h))
__device__ __forceinline__ u64 dup2(float a) {
    u64 r;
    asm("mov.b64 %0, {%1, %1};" : "=l"(r) : "r"(__float_as_uint(a)));
    return r;
}

// ---------------- device scratch ----------------------------------------------
__device__ float d_Cv[NWW * NXX];
__device__ float d_Dv[NWW * NUU];
__device__ float d_X[NXX * NXX];
__device__ float d_X2[NXX * NXX];
__device__ float d_T1[NXX * NXX];
__device__ float d_Ahat[NXX * NXX];
__device__ float d_Bhat[NXX * NWW];
__device__ float d_B2hat[NXX * NUU];
__device__ float d_fbhat[NXX];
__device__ float d_G1[(size_t)TSTEP * BATCH * NWW];     // [t][b][j]
__device__ float d_G2[(size_t)TSTEP * BATCH * NXX];     // [t][b][x]
__device__ float d_states[(size_t)TSTEP * BATCH * NXX]; // [t][b][x]
__device__ float d_Wb[(size_t)TSTEP * BATCH * NWW];     // [t][b][j]
__device__ float d_hbuf[2 * GROUPS * NXX * BGS];  // [parity][g][x][b8]
__device__ float d_wvec[GROUPS * NWW * BGS];      // [g][j][b8]
__device__ unsigned g_cw[GROUPS * 8 * 32];        // per-group per-octile w flags (128B pad)
__device__ unsigned g_ch[GROUPS * 8 * 32];        // per-group per-octile h flags
__device__ unsigned g_pcnt;                       // prep-gemm grid barrier

// ---------------- sync primitives ---------------------------------------------
__device__ __forceinline__ void rel_add1(unsigned* cnt) {
    asm volatile("red.release.gpu.add.u32 [%0], 1;" :: "l"(cnt) : "memory");
}
__device__ __forceinline__ void wait_cnt(unsigned* cnt, unsigned target) {
    unsigned v;
    do {
        asm volatile("ld.acquire.gpu.u32 %0, [%1];" : "=r"(v) : "l"(cnt) : "memory");
    } while (v < target);
}
__device__ __forceinline__ float4 ldcg4(const float4* p) {
    float4 v;
    asm volatile("ld.global.cg.v4.f32 {%0,%1,%2,%3}, [%4];"
                 : "=f"(v.x), "=f"(v.y), "=f"(v.z), "=f"(v.w) : "l"(p));
    return v;
}

// ---------------- prep: Cv, Dv, X0 = 2I - E, reset prep barrier ---------------
__global__ void prep_kernel(const float* __restrict__ C2, const float* __restrict__ mult,
                            const float* __restrict__ Dt, const float* __restrict__ E) {
    int i = blockIdx.x * blockDim.x + threadIdx.x;
    int stride = gridDim.x * blockDim.x;
    if (i == 0) g_pcnt = 0u;
    for (int idx = i; idx < NWW * NXX; idx += stride) {
        int r = idx / NXX;
        d_Cv[idx] = C2[idx] / mult[r];
    }
    for (int idx = i; idx < NWW * NUU; idx += stride) {
        int r = idx / NUU;
        d_Dv[idx] = Dt[idx] / mult[r];
    }
    for (int idx = i; idx < NXX * NXX; idx += stride) {
        int r = idx / NXX, c = idx % NXX;
        d_X[idx] = (r == c ? 2.0f : 0.0f) - E[idx];
    }
}

// ---------------- fused prep GEMM chain (persistent, 64 CTAs) -----------------
__device__ __forceinline__ void gemm_tile(const float* __restrict__ A, const float* __restrict__ Bm,
                                          float* __restrict__ C, int N, int K, int mode,
                                          int bx, int by,
                                          float (*As)[16][64], float (*Bs)[16][64]) {
    int tid = threadIdx.x;
    int tx = tid & 15, ty = tid >> 4;
    int ar = tid >> 2, ac = (tid & 3) << 2;
    int br = tid >> 4, bc = (tid & 15) << 2;
    const float* Aptr = A + (size_t)(by * 64 + ar) * K + ac;
    const float* Bptr = Bm + (size_t)br * N + bx * 64 + bc;

    float4 av = *(const float4*)Aptr;
    float4 bv = *(const float4*)Bptr;
    As[0][ac + 0][ar] = av.x; As[0][ac + 1][ar] = av.y;
    As[0][ac + 2][ar] = av.z; As[0][ac + 3][ar] = av.w;
    *(float4*)&Bs[0][br][bc] = bv;
    __syncthreads();

    float acc[4][4] = {};
    int buf = 0;
    for (int k0 = 16; k0 <= K; k0 += 16) {
        if (k0 < K) {
            av = *(const float4*)(Aptr + k0);
            bv = *(const float4*)(Bptr + (size_t)k0 * N);
        }
#pragma unroll
        for (int k = 0; k < 16; k++) {
            float4 a = *(const float4*)&As[buf][k][ty * 4];
            float4 b = *(const float4*)&Bs[buf][k][tx * 4];
            acc[0][0] = fmaf(a.x, b.x, acc[0][0]); acc[0][1] = fmaf(a.x, b.y, acc[0][1]);
            acc[0][2] = fmaf(a.x, b.z, acc[0][2]); acc[0][3] = fmaf(a.x, b.w, acc[0][3]);
            acc[1][0] = fmaf(a.y, b.x, acc[1][0]); acc[1][1] = fmaf(a.y, b.y, acc[1][1]);
            acc[1][2] = fmaf(a.y, b.z, acc[1][2]); acc[1][3] = fmaf(a.y, b.w, acc[1][3]);
            acc[2][0] = fmaf(a.z, b.x, acc[2][0]); acc[2][1] = fmaf(a.z, b.y, acc[2][1]);
            acc[2][2] = fmaf(a.z, b.z, acc[2][2]); acc[2][3] = fmaf(a.z, b.w, acc[2][3]);
            acc[3][0] = fmaf(a.w, b.x, acc[3][0]); acc[3][1] = fmaf(a.w, b.y, acc[3][1]);
            acc[3][2] = fmaf(a.w, b.z, acc[3][2]); acc[3][3] = fmaf(a.w, b.w, acc[3][3]);
        }
        if (k0 < K) {
            int nb = buf ^ 1;
            As[nb][ac + 0][ar] = av.x; As[nb][ac + 1][ar] = av.y;
            As[nb][ac + 2][ar] = av.z; As[nb][ac + 3][ar] = av.w;
            *(float4*)&Bs[nb][br][bc] = bv;
        }
        __syncthreads();
        buf ^= 1;
    }
#pragma unroll
    for (int i = 0; i < 4; i++) {
        int r = by * 64 + ty * 4 + i;
        float o[4];
#pragma unroll
        for (int j = 0; j < 4; j++) {
            int cx = bx * 64 + tx * 4 + j;
            float v = acc[i][j];
            if (mode) v = (r == cx ? 2.0f : 0.0f) - v;
            o[j] = v;
        }
        *(float4*)&C[(size_t)r * N + bx * 64 + tx * 4] = make_float4(o[0], o[1], o[2], o[3]);
    }
}

__device__ __forceinline__ void gbar(unsigned gen) {
    __threadfence();
    __syncthreads();
    if (threadIdx.x == 0) {
        rel_add1(&g_pcnt);
        wait_cnt(&g_pcnt, 64u * gen);
    }
    __syncthreads();
}

__global__ void __launch_bounds__(256, 1) prepgemm_kernel(
        const float* __restrict__ E, const float* __restrict__ F_w,
        const float* __restrict__ F_b, const float* __restrict__ B1_w,
        const float* __restrict__ B2_w) {
    __shared__ float As[2][16][64];
    __shared__ float Bs[2][16][64];
    int cta = blockIdx.x;
    int bx = cta & 7, by = cta >> 3;

    // Newton-Schulz: 3 iterations, X0 in d_X
    gemm_tile(E, d_X, d_T1, 512, 512, 1, bx, by, As, Bs);  gbar(1);
    gemm_tile(d_X, d_T1, d_X2, 512, 512, 0, bx, by, As, Bs); gbar(2);
    gemm_tile(E, d_X2, d_T1, 512, 512, 1, bx, by, As, Bs); gbar(3);
    gemm_tile(d_X2, d_T1, d_X, 512, 512, 0, bx, by, As, Bs); gbar(4);
    gemm_tile(E, d_X, d_T1, 512, 512, 1, bx, by, As, Bs);  gbar(5);
    gemm_tile(d_X, d_T1, d_X2, 512, 512, 0, bx, by, As, Bs); gbar(6);
    // d_X2 = Einv
    gemm_tile(d_X2, F_w, d_Ahat, 512, 512, 0, bx, by, As, Bs);
    gemm_tile(d_X2, B1_w, d_Bhat, 512, 512, 0, bx, by, As, Bs);
    if (cta < 8) {
        gemm_tile(d_X2, B2_w, d_B2hat, 64, 512, 0, 0, cta, As, Bs);
    } else if (cta < 16 && threadIdx.x < 64) {
        int r = (cta - 8) * 64 + threadIdx.x;
        float s = 0.f;
        for (int k = 0; k < NXX; k++) s = fmaf(d_X2[(size_t)r * NXX + k], F_b[k], s);
        d_fbhat[r] = s;
    }
}

// ---------------- u projections: out[(t*B + b)*J + j] -------------------------
__global__ void uproj_kernel(const float* __restrict__ u, const float* __restrict__ M,
                             const float* __restrict__ bias, float* __restrict__ out, int J) {
    __shared__ float U_s[NUU][65];
    __shared__ float M_s[64][65];
    int tid = threadIdx.x;
    int j0 = blockIdx.x * 64, t0 = blockIdx.y * 64, b = blockIdx.z;
    for (int i = tid; i < 64 * 64; i += 256) {
        int kk = i >> 6, tt = i & 63;
        U_s[kk][tt] = u[(size_t)b * NUU * TSTEP + (size_t)kk * TSTEP + t0 + tt];
    }
    for (int i = tid; i < 64 * 64; i += 256) {
        int j = i >> 6, k = i & 63;
        M_s[j][k] = M[(size_t)(j0 + j) * NUU + k];
    }
    __syncthreads();
    int lane = tid & 31, wg = tid >> 5;
    float acc0[8] = {}, acc1[8] = {};
    for (int k = 0; k < 64; k++) {
        float u0 = U_s[k][lane], u1 = U_s[k][lane + 32];
#pragma unroll
        for (int j = 0; j < 8; j++) {
            float m = M_s[wg * 8 + j][k];
            acc0[j] = fmaf(u0, m, acc0[j]);
            acc1[j] = fmaf(u1, m, acc1[j]);
        }
    }
    int jj0 = j0 + wg * 8;
    float bsv[8];
#pragma unroll
    for (int j = 0; j < 8; j++) bsv[j] = bias[jj0 + j];
    size_t r0 = ((size_t)(t0 + lane) * BATCH + b) * J + jj0;
    size_t r1 = ((size_t)(t0 + lane + 32) * BATCH + b) * J + jj0;
    *(float4*)&out[r0]     = make_float4(acc0[0] + bsv[0], acc0[1] + bsv[1], acc0[2] + bsv[2], acc0[3] + bsv[3]);
    *(float4*)&out[r0 + 4] = make_float4(acc0[4] + bsv[4], acc0[5] + bsv[5], acc0[6] + bsv[6], acc0[7] + bsv[7]);
    *(float4*)&out[r1]     = make_float4(acc1[0] + bsv[0], acc1[1] + bsv[1], acc1[2] + bsv[2], acc1[3] + bsv[3]);
    *(float4*)&out[r1 + 4] = make_float4(acc1[4] + bsv[4], acc1[5] + bsv[5], acc1[6] + bsv[6], acc1[7] + bsv[7]);
}

// ---------------- init --------------------------------------------------------
__global__ void init_kernel() {
    int i = blockIdx.x * blockDim.x + threadIdx.x;
    int stride = gridDim.x * blockDim.x;
    for (int idx = i; idx < GROUPS * 8 * 32; idx += stride) {
        g_cw[idx] = 0u;
        g_ch[idx] = 0u;
    }
    for (int idx = i; idx < 2 * GROUPS * NXX * BGS; idx += stride) d_hbuf[idx] = 0.f;
    for (int idx = i; idx < BATCH * NXX; idx += stride) d_states[idx] = 0.f;  // t=0
}

// ---------------- f32x2 dot: 8 row-pairs x 16 k (interleaved), one batch col --
// hp = h_s + b (stride BGS per k); wkb = [k][16 rows] f32; acc = 8 u64 row-pairs
__device__ __forceinline__ void dotp2(const float* __restrict__ hp,
                                      const float* __restrict__ wkb,
                                      int kbase, u64* __restrict__ acc) {
#pragma unroll
    for (int i = 0; i < 16; i++) {
        int k = kbase + 4 * i;
        u64 h2 = dup2(hp[k * BGS]);
        const ulonglong2* wp = (const ulonglong2*)(wkb + k * ROWS);
        ulonglong2 w01 = wp[0], w23 = wp[1], w45 = wp[2], w67 = wp[3];
        FMA2(acc[0], w01.x, h2); FMA2(acc[1], w01.y, h2);
        FMA2(acc[2], w23.x, h2); FMA2(acc[3], w23.y, h2);
        FMA2(acc[4], w45.x, h2); FMA2(acc[5], w45.y, h2);
        FMA2(acc[6], w67.x, h2); FMA2(acc[7], w67.y, h2);
    }
}

// ---------------- persistent sequential recurrence (dataflow flags) -----------
// 4 groups x 32 CTAs; group g: batches [8g, 8g+8); CTA: 16 rows.
// Per-octile flags; leader arrives (4/CTA/phase, target 16 per step).
__global__ void __launch_bounds__(RTHR, 1) recur_kernel() {
    extern __shared__ float sm[];
    float* wC  = sm;                 // [512][16]
    float* wA  = wC + 8192;
    float* wB  = wA + 8192;
    float* h_s = wB + 8192;          // [512][8]
    float* w_s = h_s + NXX * BGS;    // [512][8]
    float* pW  = w_s + NWW * BGS;    // [32][PST]
    float* pA  = pW + 32 * PST;
    float* pB  = pA + 32 * PST;

    int tid  = threadIdx.x;
    int cta  = blockIdx.x;
    int g    = cta >> 5;
    int lc   = cta & 31;
    int j0   = lc * ROWS;
    int warp = tid >> 5, lane = tid & 31;
    int kh = lane >> 3, b = lane & 7;
    int rrow = tid & 15, rb = tid >> 4;        // reduce mapping (tid<128)
    int bb = g * BGS + rb;

    unsigned* cw_arr = &g_cw[(g * 8 + (lc >> 2)) * 32];   // my arrive flag (w)
    unsigned* ch_arr = &g_ch[(g * 8 + (lc >> 2)) * 32];   // my arrive flag (h)
    unsigned* cw_poll = &g_cw[(g * 8 + warp) * 32];       // my warp's dependency (w)
    unsigned* ch_poll = &g_ch[(g * 8 + warp) * 32];       // my warp's dependency (h)

    float* wg = d_wvec + g * NWW * BGS;

    // stage weight slices [k][row] (resident for whole kernel)
    for (int i = tid; i < 8192; i += RTHR) {
        int k = i >> 4, c = i & 15;
        wC[i] = d_Cv[(size_t)(j0 + c) * NXX + k];
        wA[i] = d_Ahat[(size_t)(j0 + c) * NXX + k];
        wB[i] = d_Bhat[(size_t)(j0 + c) * NWW + k];
    }
    __syncthreads();

    int kbase = warp * 64 + kh;
    int slot = warp * 4 + kh;
    // partial outputs: u64 row-pair r at f32 index b*16 + 2r
    u64* ppW = (u64*)(pW + slot * PST + b * 16);
    u64* ppA = (u64*)(pA + slot * PST + b * 16);
    u64* ppB = (u64*)(pB + slot * PST + b * 16);
    int roff = rb * 16 + rrow;

    for (int t = 0; t < TSTEP; t++) {
        // prefetch G terms (in flight during poll)
        float g1 = 0.f, g2 = 0.f;
        if (tid < 128) {
            g1 = __ldcg(&d_G1[((size_t)t * BATCH + bb) * NWW + j0 + rrow]);
            if (t < TSTEP - 1)
                g2 = __ldcg(&d_G2[((size_t)t * BATCH + bb) * NXX + j0 + rrow]);
        }
        // wait for this warp's h(t) octile, copy it
        if (t > 0) {
            if (lane == 0) wait_cnt(ch_poll, 16u * (unsigned)t);
            __syncwarp();
        }
        {
            const float4* src = (const float4*)(d_hbuf +
                ((size_t)(t & 1) * GROUPS + g) * (NXX * BGS)) + warp * 128;
            float4* dst = (float4*)h_s + warp * 128;
#pragma unroll
            for (int i = 0; i < 4; i++) dst[lane + 32 * i] = ldcg4(&src[lane + 32 * i]);
        }
        __syncwarp();
        // phase A: Cv @ h  (f32x2 over row pairs)
        {
            u64 acc[8] = {};
            dotp2(h_s + b, wC, kbase, acc);
#pragma unroll
            for (int r = 0; r < 8; r++) ppW[r] = acc[r];
        }
        __syncthreads();  // S1: pW complete
        if (tid < 128) {
            float v = g1;
#pragma unroll
            for (int p = 0; p < 32; p++) v += pW[p * PST + roff];
            v = fmaxf(v, 0.f);
            wg[(j0 + rrow) * BGS + rb] = v;          // exchange store first
            __syncwarp();
            if (lane == 0) rel_add1(cw_arr);         // leader release-arrive
            d_Wb[((size_t)t * BATCH + bb) * NWW + j0 + rrow] = v;  // trajectory after
        }
        if (t == TSTEP - 1) break;
        // Ahat @ h (independent of w — overlaps other CTAs' phase A)
        {
            u64 acc[8] = {};
            dotp2(h_s + b, wA, kbase, acc);
#pragma unroll
            for (int r = 0; r < 8; r++) ppA[r] = acc[r];
        }
        // wait for this warp's w(t) octile, copy it
        if (lane == 0) wait_cnt(cw_poll, 16u * (unsigned)(t + 1));
        __syncwarp();
        {
            const float4* src = (const float4*)wg + warp * 128;
            float4* dst = (float4*)w_s + warp * 128;
#pragma unroll
            for (int i = 0; i < 4; i++) dst[lane + 32 * i] = ldcg4(&src[lane + 32 * i]);
        }
        __syncwarp();
        // Bhat @ w
        {
            u64 acc[8] = {};
            dotp2(w_s + b, wB, kbase, acc);
#pragma unroll
            for (int r = 0; r < 8; r++) ppB[r] = acc[r];
        }
        __syncthreads();  // S3: pA, pB complete
        if (tid < 128) {
            float v = g2;
#pragma unroll
            for (int p = 0; p < 32; p++)
                v += pA[p * PST + roff] + pB[p * PST + roff];
            d_hbuf[((size_t)((t + 1) & 1) * GROUPS + g) * (NXX * BGS) + (j0 + rrow) * BGS + rb] = v;
            __syncwarp();
            if (lane == 0) rel_add1(ch_arr);
            d_states[((size_t)(t + 1) * BATCH + bb) * NXX + j0 + rrow] = v;
        }
    }
}

// ---------------- epilogue: y = states@C1.T + W@D11.T + u@D12.T + by ----------
__global__ void yfinal_kernel(const float* __restrict__ u, const float* __restrict__ C1,
                              const float* __restrict__ D11, const float* __restrict__ D12,
                              const float* __restrict__ by, float* __restrict__ out) {
    __shared__ float As[64][65];
    __shared__ float Bs[64][68];
    int tid = threadIdx.x;
    int tx = tid & 15, ty = tid >> 4;
    int t0 = blockIdx.x * 64, b = blockIdx.y;
    float acc[4][4] = {};
    for (int seg = 0; seg < 3; seg++) {
        int nchunk = (seg == 2) ? 1 : 8;
        const float* Am = (seg == 0) ? C1 : (seg == 1) ? D11 : D12;
        int Ksz = (seg == 2) ? 64 : 512;
        for (int ch = 0; ch < nchunk; ch++) {
            int x0 = ch * 64;
            for (int i = tid; i < 64 * 64; i += 256) {
                int j = i >> 6, k = i & 63;
                As[j][k] = Am[(size_t)j * Ksz + x0 + k];
            }
            if (seg == 2) {
                for (int i = tid; i < 64 * 64; i += 256) {
                    int k = i >> 6, tt = i & 63;
                    Bs[k][tt] = u[((size_t)b * NUU + k) * TSTEP + t0 + tt];
                }
            } else {
                const float* S = (seg == 0) ? d_states : d_Wb;
                for (int i = tid; i < 64 * 64; i += 256) {
                    int tt = i >> 6, xx = i & 63;
                    Bs[xx][tt] = S[((size_t)(t0 + tt) * BATCH + b) * 512 + x0 + xx];
                }
            }
            __syncthreads();
#pragma unroll 8
            for (int k = 0; k < 64; k++) {
                float a0 = As[ty * 4 + 0][k];
                float a1 = As[ty * 4 + 1][k];
                float a2 = As[ty * 4 + 2][k];
                float a3 = As[ty * 4 + 3][k];
                float4 bv = *(const float4*)&Bs[k][tx * 4];
                acc[0][0] = fmaf(a0, bv.x, acc[0][0]); acc[0][1] = fmaf(a0, bv.y, acc[0][1]);
                acc[0][2] = fmaf(a0, bv.z, acc[0][2]); acc[0][3] = fmaf(a0, bv.w, acc[0][3]);
                acc[1][0] = fmaf(a1, bv.x, acc[1][0]); acc[1][1] = fmaf(a1, bv.y, acc[1][1]);
                acc[1][2] = fmaf(a1, bv.z, acc[1][2]); acc[1][3] = fmaf(a1, bv.w, acc[1][3]);
                acc[2][0] = fmaf(a2, bv.x, acc[2][0]); acc[2][1] = fmaf(a2, bv.y, acc[2][1]);
                acc[2][2] = fmaf(a2, bv.z, acc[2][2]); acc[2][3] = fmaf(a2, bv.w, acc[2][3]);
                acc[3][0] = fmaf(a3, bv.x, acc[3][0]); acc[3][1] = fmaf(a3, bv.y, acc[3][1]);
                acc[3][2] = fmaf(a3, bv.z, acc[3][2]); acc[3][3] = fmaf(a3, bv.w, acc[3][3]);
            }
            __syncthreads();
        }
    }
#pragma unroll
    for (int i = 0; i < 4; i++) {
        int j = ty * 4 + i;
        float bj = by[j];
        float4 o = make_float4(acc[i][0] + bj, acc[i][1] + bj, acc[i][2] + bj, acc[i][3] + bj);
        *(float4*)&out[((size_t)b * NYY + j) * TSTEP + t0 + tx * 4] = o;
    }
}

// ---------------- launch ------------------------------------------------------
extern "C" void kernel_launch(void* const* d_in, const int* in_sizes, int n_in,
                              void* d_out, int out_size) {
    const float* u      = (const float*)d_in[0];
    const float* E      = (const float*)d_in[1];
    const float* F_w    = (const float*)d_in[2];
    const float* F_b    = (const float*)d_in[3];
    const float* B1_w   = (const float*)d_in[4];
    const float* B2_w   = (const float*)d_in[5];
    const float* C2tild = (const float*)d_in[6];
    const float* bv     = (const float*)d_in[7];
    const float* Dtild  = (const float*)d_in[8];
    const float* C1_w   = (const float*)d_in[9];
    const float* D11_w  = (const float*)d_in[10];
    const float* D12_w  = (const float*)d_in[11];
    const float* by     = (const float*)d_in[12];
    const float* multis = (const float*)d_in[13];
    float* out = (float*)d_out;

    float *Dv, *G1, *G2, *B2hat, *fbhat;
    cudaGetSymbolAddress((void**)&Dv,    d_Dv);
    cudaGetSymbolAddress((void**)&G1,    d_G1);
    cudaGetSymbolAddress((void**)&G2,    d_G2);
    cudaGetSymbolAddress((void**)&B2hat, d_B2hat);
    cudaGetSymbolAddress((void**)&fbhat, d_fbhat);

    const int SMEM_RECUR = (3 * 8192 + 2 * 4096 + 3 * 32 * PST) * 4;
    cudaFuncSetAttribute(recur_kernel, cudaFuncAttributeMaxDynamicSharedMemorySize, SMEM_RECUR);

    // 1) Cv, Dv, X0 = 2I - E, reset prep barrier
    prep_kernel<<<256, 256>>>(C2tild, multis, Dtild, E);
    // 2) fused Newton-Schulz (3 iters) + weight folding
    prepgemm_kernel<<<64, 256>>>(E, F_w, F_b, B1_w, B2_w);
    // 3,4) input-driven terms
    uproj_kernel<<<dim3(8, 16, 32), 256>>>(u, Dv, bv, G1, NWW);
    uproj_kernel<<<dim3(8, 16, 32), 256>>>(u, B2hat, fbhat, G2, NXX);
    // 5) init flags + state
    init_kernel<<<64, 256>>>();
    // 6) sequential recurrence
    recur_kernel<<<RCTAS, RTHR, SMEM_RECUR>>>();
    // 7) epilogue
    yfinal_kernel<<<dim3(16, 32), 256>>>(u, C1_w, D11_w, D12_w, by, out);
}

// round 15
// speedup vs baseline: 21.5762x; 1.4858x over previous
#include <cuda_runtime.h>
#include <cstddef>
#include <cstdint>

#define BATCH 32
#define NUU   64
#define NYY   64
#define NXX   512
#define NWW   512
#define TSTEP 1024
#define RCTAS 128
#define RTHR  256
#define GROUPS 4
#define GCTAS 32     // CTAs per group
#define BGS   8      // batches per group
#define ROWS  16     // rows per CTA
#define PST   136    // partial-buffer stride (floats)

typedef unsigned long long u64;

// ---------------- packed f32x2 helpers ----------------------------------------
#define FMA2(acc, w, h) asm("fma.rn.f32x2 %0, %1, %2, %0;" : "+l"(acc) : "l"(w), "l"(h))
__device__ __forceinline__ u64 dup2(float a) {
    u64 r;
    asm("mov.b64 %0, {%1, %1};" : "=l"(r) : "r"(__float_as_uint(a)));
    return r;
}

// ---------------- device scratch ----------------------------------------------
__device__ float d_Cv[NWW * NXX];
__device__ float d_Dv[NWW * NUU];
__device__ float d_X[NXX * NXX];
__device__ float d_X2[NXX * NXX];
__device__ float d_T1[NXX * NXX];
__device__ float d_Ahat[NXX * NXX];
__device__ float d_Bhat[NXX * NWW];
__device__ float d_B2hat[NXX * NUU];
__device__ float d_fbhat[NXX];
__device__ float d_G1[(size_t)TSTEP * BATCH * NWW];     // [t][b][j]
__device__ float d_G2[(size_t)TSTEP * BATCH * NXX];     // [t][b][x]
__device__ float d_states[(size_t)TSTEP * BATCH * NXX]; // [t][b][x]
__device__ float d_Wb[(size_t)TSTEP * BATCH * NWW];     // [t][b][j]
__device__ float d_hbuf[2 * GROUPS * NXX * BGS];  // [parity][g][x][b8]
__device__ float d_wvec[GROUPS * NWW * BGS];      // [g][j][b8]
__device__ unsigned g_cw[GROUPS * 8 * 32];        // per-group per-octile w flags (128B pad)
__device__ unsigned g_ch[GROUPS * 8 * 32];        // per-group per-octile h flags
__device__ unsigned g_pcnt;                       // prep-gemm grid barrier

// ---------------- sync primitives ---------------------------------------------
__device__ __forceinline__ void rel_add1(unsigned* cnt) {
    asm volatile("red.release.gpu.add.u32 [%0], 1;" :: "l"(cnt) : "memory");
}
__device__ __forceinline__ void wait_cnt(unsigned* cnt, unsigned target) {
    unsigned v;
    do {
        asm volatile("ld.acquire.gpu.u32 %0, [%1];" : "=r"(v) : "l"(cnt) : "memory");
    } while (v < target);
}
__device__ __forceinline__ float4 ldcg4(const float4* p) {
    float4 v;
    asm volatile("ld.global.cg.v4.f32 {%0,%1,%2,%3}, [%4];"
                 : "=f"(v.x), "=f"(v.y), "=f"(v.z), "=f"(v.w) : "l"(p));
    return v;
}

// ---------------- prep: Cv, Dv, X0 = 2I - E, reset prep barrier ---------------
__global__ void prep_kernel(const float* __restrict__ C2, const float* __restrict__ mult,
                            const float* __restrict__ Dt, const float* __restrict__ E) {
    int i = blockIdx.x * blockDim.x + threadIdx.x;
    int stride = gridDim.x * blockDim.x;
    if (i == 0) g_pcnt = 0u;
    for (int idx = i; idx < NWW * NXX; idx += stride) {
        int r = idx / NXX;
        d_Cv[idx] = C2[idx] / mult[r];
    }
    for (int idx = i; idx < NWW * NUU; idx += stride) {
        int r = idx / NUU;
        d_Dv[idx] = Dt[idx] / mult[r];
    }
    for (int idx = i; idx < NXX * NXX; idx += stride) {
        int r = idx / NXX, c = idx % NXX;
        d_X[idx] = (r == c ? 2.0f : 0.0f) - E[idx];
    }
}

// ---------------- fused prep GEMM chain (persistent, 64 CTAs) -----------------
__device__ __forceinline__ void gemm_tile(const float* __restrict__ A, const float* __restrict__ Bm,
                                          float* __restrict__ C, int N, int K, int mode,
                                          int bx, int by,
                                          float (*As)[16][64], float (*Bs)[16][64]) {
    int tid = threadIdx.x;
    int tx = tid & 15, ty = tid >> 4;
    int ar = tid >> 2, ac = (tid & 3) << 2;
    int br = tid >> 4, bc = (tid & 15) << 2;
    const float* Aptr = A + (size_t)(by * 64 + ar) * K + ac;
    const float* Bptr = Bm + (size_t)br * N + bx * 64 + bc;

    float4 av = *(const float4*)Aptr;
    float4 bv = *(const float4*)Bptr;
    As[0][ac + 0][ar] = av.x; As[0][ac + 1][ar] = av.y;
    As[0][ac + 2][ar] = av.z; As[0][ac + 3][ar] = av.w;
    *(float4*)&Bs[0][br][bc] = bv;
    __syncthreads();

    float acc[4][4] = {};
    int buf = 0;
    for (int k0 = 16; k0 <= K; k0 += 16) {
        if (k0 < K) {
            av = *(const float4*)(Aptr + k0);
            bv = *(const float4*)(Bptr + (size_t)k0 * N);
        }
#pragma unroll
        for (int k = 0; k < 16; k++) {
            float4 a = *(const float4*)&As[buf][k][ty * 4];
            float4 b = *(const float4*)&Bs[buf][k][tx * 4];
            acc[0][0] = fmaf(a.x, b.x, acc[0][0]); acc[0][1] = fmaf(a.x, b.y, acc[0][1]);
            acc[0][2] = fmaf(a.x, b.z, acc[0][2]); acc[0][3] = fmaf(a.x, b.w, acc[0][3]);
            acc[1][0] = fmaf(a.y, b.x, acc[1][0]); acc[1][1] = fmaf(a.y, b.y, acc[1][1]);
            acc[1][2] = fmaf(a.y, b.z, acc[1][2]); acc[1][3] = fmaf(a.y, b.w, acc[1][3]);
            acc[2][0] = fmaf(a.z, b.x, acc[2][0]); acc[2][1] = fmaf(a.z, b.y, acc[2][1]);
            acc[2][2] = fmaf(a.z, b.z, acc[2][2]); acc[2][3] = fmaf(a.z, b.w, acc[2][3]);
            acc[3][0] = fmaf(a.w, b.x, acc[3][0]); acc[3][1] = fmaf(a.w, b.y, acc[3][1]);
            acc[3][2] = fmaf(a.w, b.z, acc[3][2]); acc[3][3] = fmaf(a.w, b.w, acc[3][3]);
        }
        if (k0 < K) {
            int nb = buf ^ 1;
            As[nb][ac + 0][ar] = av.x; As[nb][ac + 1][ar] = av.y;
            As[nb][ac + 2][ar] = av.z; As[nb][ac + 3][ar] = av.w;
            *(float4*)&Bs[nb][br][bc] = bv;
        }
        __syncthreads();
        buf ^= 1;
    }
#pragma unroll
    for (int i = 0; i < 4; i++) {
        int r = by * 64 + ty * 4 + i;
        float o[4];
#pragma unroll
        for (int j = 0; j < 4; j++) {
            int cx = bx * 64 + tx * 4 + j;
            float v = acc[i][j];
            if (mode) v = (r == cx ? 2.0f : 0.0f) - v;
            o[j] = v;
        }
        *(float4*)&C[(size_t)r * N + bx * 64 + tx * 4] = make_float4(o[0], o[1], o[2], o[3]);
    }
}

__device__ __forceinline__ void gbar(unsigned gen) {
    __threadfence();
    __syncthreads();
    if (threadIdx.x == 0) {
        rel_add1(&g_pcnt);
        wait_cnt(&g_pcnt, 64u * gen);
    }
    __syncthreads();
}

__global__ void __launch_bounds__(256, 1) prepgemm_kernel(
        const float* __restrict__ E, const float* __restrict__ F_w,
        const float* __restrict__ F_b, const float* __restrict__ B1_w,
        const float* __restrict__ B2_w) {
    __shared__ float As[2][16][64];
    __shared__ float Bs[2][16][64];
    int cta = blockIdx.x;
    int bx = cta & 7, by = cta >> 3;

    // Newton-Schulz: 3 iterations, X0 in d_X
    gemm_tile(E, d_X, d_T1, 512, 512, 1, bx, by, As, Bs);  gbar(1);
    gemm_tile(d_X, d_T1, d_X2, 512, 512, 0, bx, by, As, Bs); gbar(2);
    gemm_tile(E, d_X2, d_T1, 512, 512, 1, bx, by, As, Bs); gbar(3);
    gemm_tile(d_X2, d_T1, d_X, 512, 512, 0, bx, by, As, Bs); gbar(4);
    gemm_tile(E, d_X, d_T1, 512, 512, 1, bx, by, As, Bs);  gbar(5);
    gemm_tile(d_X, d_T1, d_X2, 512, 512, 0, bx, by, As, Bs); gbar(6);
    // d_X2 = Einv
    gemm_tile(d_X2, F_w, d_Ahat, 512, 512, 0, bx, by, As, Bs);
    gemm_tile(d_X2, B1_w, d_Bhat, 512, 512, 0, bx, by, As, Bs);
    if (cta < 8) {
        gemm_tile(d_X2, B2_w, d_B2hat, 64, 512, 0, 0, cta, As, Bs);
    } else if (cta < 16 && threadIdx.x < 64) {
        int r = (cta - 8) * 64 + threadIdx.x;
        float s = 0.f;
        for (int k = 0; k < NXX; k++) s = fmaf(d_X2[(size_t)r * NXX + k], F_b[k], s);
        d_fbhat[r] = s;
    }
}

// ---------------- u projections: out[(t*B + b)*J + j] -------------------------
__global__ void uproj_kernel(const float* __restrict__ u, const float* __restrict__ M,
                             const float* __restrict__ bias, float* __restrict__ out, int J) {
    __shared__ float U_s[NUU][65];
    __shared__ float M_s[64][65];
    int tid = threadIdx.x;
    int j0 = blockIdx.x * 64, t0 = blockIdx.y * 64, b = blockIdx.z;
    for (int i = tid; i < 64 * 64; i += 256) {
        int kk = i >> 6, tt = i & 63;
        U_s[kk][tt] = u[(size_t)b * NUU * TSTEP + (size_t)kk * TSTEP + t0 + tt];
    }
    for (int i = tid; i < 64 * 64; i += 256) {
        int j = i >> 6, k = i & 63;
        M_s[j][k] = M[(size_t)(j0 + j) * NUU + k];
    }
    __syncthreads();
    int lane = tid & 31, wg = tid >> 5;
    float acc0[8] = {}, acc1[8] = {};
    for (int k = 0; k < 64; k++) {
        float u0 = U_s[k][lane], u1 = U_s[k][lane + 32];
#pragma unroll
        for (int j = 0; j < 8; j++) {
            float m = M_s[wg * 8 + j][k];
            acc0[j] = fmaf(u0, m, acc0[j]);
            acc1[j] = fmaf(u1, m, acc1[j]);
        }
    }
    int jj0 = j0 + wg * 8;
    float bsv[8];
#pragma unroll
    for (int j = 0; j < 8; j++) bsv[j] = bias[jj0 + j];
    size_t r0 = ((size_t)(t0 + lane) * BATCH + b) * J + jj0;
    size_t r1 = ((size_t)(t0 + lane + 32) * BATCH + b) * J + jj0;
    *(float4*)&out[r0]     = make_float4(acc0[0] + bsv[0], acc0[1] + bsv[1], acc0[2] + bsv[2], acc0[3] + bsv[3]);
    *(float4*)&out[r0 + 4] = make_float4(acc0[4] + bsv[4], acc0[5] + bsv[5], acc0[6] + bsv[6], acc0[7] + bsv[7]);
    *(float4*)&out[r1]     = make_float4(acc1[0] + bsv[0], acc1[1] + bsv[1], acc1[2] + bsv[2], acc1[3] + bsv[3]);
    *(float4*)&out[r1 + 4] = make_float4(acc1[4] + bsv[4], acc1[5] + bsv[5], acc1[6] + bsv[6], acc1[7] + bsv[7]);
}

// ---------------- init --------------------------------------------------------
__global__ void init_kernel() {
    int i = blockIdx.x * blockDim.x + threadIdx.x;
    int stride = gridDim.x * blockDim.x;
    for (int idx = i; idx < GROUPS * 8 * 32; idx += stride) {
        g_cw[idx] = 0u;
        g_ch[idx] = 0u;
    }
    for (int idx = i; idx < 2 * GROUPS * NXX * BGS; idx += stride) d_hbuf[idx] = 0.f;
    for (int idx = i; idx < BATCH * NXX; idx += stride) d_states[idx] = 0.f;  // t=0
}

// ---------------- f32x2 dot: 8 row-pairs x 16 k (interleaved), one batch col --
__device__ __forceinline__ void dotp2(const float* __restrict__ hp,
                                      const float* __restrict__ wkb,
                                      int kbase, u64* __restrict__ acc) {
#pragma unroll
    for (int i = 0; i < 16; i++) {
        int k = kbase + 4 * i;
        u64 h2 = dup2(hp[k * BGS]);
        const ulonglong2* wp = (const ulonglong2*)(wkb + k * ROWS);
        ulonglong2 w01 = wp[0], w23 = wp[1], w45 = wp[2], w67 = wp[3];
        FMA2(acc[0], w01.x, h2); FMA2(acc[1], w01.y, h2);
        FMA2(acc[2], w23.x, h2); FMA2(acc[3], w23.y, h2);
        FMA2(acc[4], w45.x, h2); FMA2(acc[5], w45.y, h2);
        FMA2(acc[6], w67.x, h2); FMA2(acc[7], w67.y, h2);
    }
}

// ---------------- persistent sequential recurrence (dataflow flags) -----------
// 4 groups x 32 CTAs; group g: batches [8g, 8g+8); CTA: 16 rows.
// Per-octile flags; ALL 128 reduce threads arrive (target 512/step) — the
// R14 leader-arrive variant regressed; wide arrives drain in parallel.
__global__ void __launch_bounds__(RTHR, 1) recur_kernel() {
    extern __shared__ float sm[];
    float* wC  = sm;                 // [512][16]
    float* wA  = wC + 8192;
    float* wB  = wA + 8192;
    float* h_s = wB + 8192;          // [512][8]
    float* w_s = h_s + NXX * BGS;    // [512][8]
    float* pW  = w_s + NWW * BGS;    // [32][PST]
    float* pA  = pW + 32 * PST;
    float* pB  = pA + 32 * PST;

    int tid  = threadIdx.x;
    int cta  = blockIdx.x;
    int g    = cta >> 5;
    int lc   = cta & 31;
    int j0   = lc * ROWS;
    int warp = tid >> 5, lane = tid & 31;
    int kh = lane >> 3, b = lane & 7;
    int rrow = tid & 15, rb = tid >> 4;        // reduce mapping (tid<128)
    int bb = g * BGS + rb;

    unsigned* cw_arr = &g_cw[(g * 8 + (lc >> 2)) * 32];   // my arrive flag (w)
    unsigned* ch_arr = &g_ch[(g * 8 + (lc >> 2)) * 32];   // my arrive flag (h)
    unsigned* cw_poll = &g_cw[(g * 8 + warp) * 32];       // my warp's dependency (w)
    unsigned* ch_poll = &g_ch[(g * 8 + warp) * 32];       // my warp's dependency (h)

    float* wg = d_wvec + g * NWW * BGS;

    // stage weight slices [k][row] (resident for whole kernel)
    for (int i = tid; i < 8192; i += RTHR) {
        int k = i >> 4, c = i & 15;
        wC[i] = d_Cv[(size_t)(j0 + c) * NXX + k];
        wA[i] = d_Ahat[(size_t)(j0 + c) * NXX + k];
        wB[i] = d_Bhat[(size_t)(j0 + c) * NWW + k];
    }
    __syncthreads();

    int kbase = warp * 64 + kh;
    int slot = warp * 4 + kh;
    u64* ppW = (u64*)(pW + slot * PST + b * 16);
    u64* ppA = (u64*)(pA + slot * PST + b * 16);
    u64* ppB = (u64*)(pB + slot * PST + b * 16);
    int roff = rb * 16 + rrow;

    for (int t = 0; t < TSTEP; t++) {
        // prefetch G terms (in flight during poll)
        float g1 = 0.f, g2 = 0.f;
        if (tid < 128) {
            g1 = __ldcg(&d_G1[((size_t)t * BATCH + bb) * NWW + j0 + rrow]);
            if (t < TSTEP - 1)
                g2 = __ldcg(&d_G2[((size_t)t * BATCH + bb) * NXX + j0 + rrow]);
        }
        // wait for this warp's h(t) octile, copy it
        if (t > 0) {
            if (lane == 0) wait_cnt(ch_poll, 512u * (unsigned)t);
            __syncwarp();
        }
        {
            const float4* src = (const float4*)(d_hbuf +
                ((size_t)(t & 1) * GROUPS + g) * (NXX * BGS)) + warp * 128;
            float4* dst = (float4*)h_s + warp * 128;
#pragma unroll
            for (int i = 0; i < 4; i++) dst[lane + 32 * i] = ldcg4(&src[lane + 32 * i]);
        }
        __syncwarp();
        // phase A: Cv @ h  (f32x2 over row pairs)
        {
            u64 acc[8] = {};
            dotp2(h_s + b, wC, kbase, acc);
#pragma unroll
            for (int r = 0; r < 8; r++) ppW[r] = acc[r];
        }
        __syncthreads();  // S1: pW complete
        if (tid < 128) {
            float v = g1;
#pragma unroll
            for (int p = 0; p < 32; p++) v += pW[p * PST + roff];
            v = fmaxf(v, 0.f);
            wg[(j0 + rrow) * BGS + rb] = v;     // exchange store (inside release set)
            rel_add1(cw_arr);                   // wide release-arrive
            d_Wb[((size_t)t * BATCH + bb) * NWW + j0 + rrow] = v;  // trajectory AFTER
        }
        if (t == TSTEP - 1) break;
        // Ahat @ h (independent of w — overlaps other CTAs' phase A)
        {
            u64 acc[8] = {};
            dotp2(h_s + b, wA, kbase, acc);
#pragma unroll
            for (int r = 0; r < 8; r++) ppA[r] = acc[r];
        }
        // wait for this warp's w(t) octile, copy it
        if (lane == 0) wait_cnt(cw_poll, 512u * (unsigned)(t + 1));
        __syncwarp();
        {
            const float4* src = (const float4*)wg + warp * 128;
            float4* dst = (float4*)w_s + warp * 128;
#pragma unroll
            for (int i = 0; i < 4; i++) dst[lane + 32 * i] = ldcg4(&src[lane + 32 * i]);
        }
        __syncwarp();
        // Bhat @ w
        {
            u64 acc[8] = {};
            dotp2(w_s + b, wB, kbase, acc);
#pragma unroll
            for (int r = 0; r < 8; r++) ppB[r] = acc[r];
        }
        __syncthreads();  // S3: pA, pB complete
        if (tid < 128) {
            float v = g2;
#pragma unroll
            for (int p = 0; p < 32; p++)
                v += pA[p * PST + roff] + pB[p * PST + roff];
            d_hbuf[((size_t)((t + 1) & 1) * GROUPS + g) * (NXX * BGS) + (j0 + rrow) * BGS + rb] = v;
            rel_add1(ch_arr);                   // wide release-arrive
            d_states[((size_t)(t + 1) * BATCH + bb) * NXX + j0 + rrow] = v;  // trajectory AFTER
        }
    }
}

// ---------------- epilogue: y = states@C1.T + W@D11.T + u@D12.T + by ----------
__global__ void yfinal_kernel(const float* __restrict__ u, const float* __restrict__ C1,
                              const float* __restrict__ D11, const float* __restrict__ D12,
                              const float* __restrict__ by, float* __restrict__ out) {
    __shared__ float As[64][65];
    __shared__ float Bs[64][68];
    int tid = threadIdx.x;
    int tx = tid & 15, ty = tid >> 4;
    int t0 = blockIdx.x * 64, b = blockIdx.y;
    float acc[4][4] = {};
    for (int seg = 0; seg < 3; seg++) {
        int nchunk = (seg == 2) ? 1 : 8;
        const float* Am = (seg == 0) ? C1 : (seg == 1) ? D11 : D12;
        int Ksz = (seg == 2) ? 64 : 512;
        for (int ch = 0; ch < nchunk; ch++) {
            int x0 = ch * 64;
            for (int i = tid; i < 64 * 64; i += 256) {
                int j = i >> 6, k = i & 63;
                As[j][k] = Am[(size_t)j * Ksz + x0 + k];
            }
            if (seg == 2) {
                for (int i = tid; i < 64 * 64; i += 256) {
                    int k = i >> 6, tt = i & 63;
                    Bs[k][tt] = u[((size_t)b * NUU + k) * TSTEP + t0 + tt];
                }
            } else {
                const float* S = (seg == 0) ? d_states : d_Wb;
                for (int i = tid; i < 64 * 64; i += 256) {
                    int tt = i >> 6, xx = i & 63;
                    Bs[xx][tt] = S[((size_t)(t0 + tt) * BATCH + b) * 512 + x0 + xx];
                }
            }
            __syncthreads();
#pragma unroll 8
            for (int k = 0; k < 64; k++) {
                float a0 = As[ty * 4 + 0][k];
                float a1 = As[ty * 4 + 1][k];
                float a2 = As[ty * 4 + 2][k];
                float a3 = As[ty * 4 + 3][k];
                float4 bv = *(const float4*)&Bs[k][tx * 4];
                acc[0][0] = fmaf(a0, bv.x, acc[0][0]); acc[0][1] = fmaf(a0, bv.y, acc[0][1]);
                acc[0][2] = fmaf(a0, bv.z, acc[0][2]); acc[0][3] = fmaf(a0, bv.w, acc[0][3]);
                acc[1][0] = fmaf(a1, bv.x, acc[1][0]); acc[1][1] = fmaf(a1, bv.y, acc[1][1]);
                acc[1][2] = fmaf(a1, bv.z, acc[1][2]); acc[1][3] = fmaf(a1, bv.w, acc[1][3]);
                acc[2][0] = fmaf(a2, bv.x, acc[2][0]); acc[2][1] = fmaf(a2, bv.y, acc[2][1]);
                acc[2][2] = fmaf(a2, bv.z, acc[2][2]); acc[2][3] = fmaf(a2, bv.w, acc[2][3]);
                acc[3][0] = fmaf(a3, bv.x, acc[3][0]); acc[3][1] = fmaf(a3, bv.y, acc[3][1]);
                acc[3][2] = fmaf(a3, bv.z, acc[3][2]); acc[3][3] = fmaf(a3, bv.w, acc[3][3]);
            }
            __syncthreads();
        }
    }
#pragma unroll
    for (int i = 0; i < 4; i++) {
        int j = ty * 4 + i;
        float bj = by[j];
        float4 o = make_float4(acc[i][0] + bj, acc[i][1] + bj, acc[i][2] + bj, acc[i][3] + bj);
        *(float4*)&out[((size_t)b * NYY + j) * TSTEP + t0 + tx * 4] = o;
    }
}

// ---------------- launch ------------------------------------------------------
extern "C" void kernel_launch(void* const* d_in, const int* in_sizes, int n_in,
                              void* d_out, int out_size) {
    const float* u      = (const float*)d_in[0];
    const float* E      = (const float*)d_in[1];
    const float* F_w    = (const float*)d_in[2];
    const float* F_b    = (const float*)d_in[3];
    const float* B1_w   = (const float*)d_in[4];
    const float* B2_w   = (const float*)d_in[5];
    const float* C2tild = (const float*)d_in[6];
    const float* bv     = (const float*)d_in[7];
    const float* Dtild  = (const float*)d_in[8];
    const float* C1_w   = (const float*)d_in[9];
    const float* D11_w  = (const float*)d_in[10];
    const float* D12_w  = (const float*)d_in[11];
    const float* by     = (const float*)d_in[12];
    const float* multis = (const float*)d_in[13];
    float* out = (float*)d_out;

    float *Dv, *G1, *G2, *B2hat, *fbhat;
    cudaGetSymbolAddress((void**)&Dv,    d_Dv);
    cudaGetSymbolAddress((void**)&G1,    d_G1);
    cudaGetSymbolAddress((void**)&G2,    d_G2);
    cudaGetSymbolAddress((void**)&B2hat, d_B2hat);
    cudaGetSymbolAddress((void**)&fbhat, d_fbhat);

    const int SMEM_RECUR = (3 * 8192 + 2 * 4096 + 3 * 32 * PST) * 4;
    cudaFuncSetAttribute(recur_kernel, cudaFuncAttributeMaxDynamicSharedMemorySize, SMEM_RECUR);

    // 1) Cv, Dv, X0 = 2I - E, reset prep barrier
    prep_kernel<<<256, 256>>>(C2tild, multis, Dtild, E);
    // 2) fused Newton-Schulz (3 iters) + weight folding
    prepgemm_kernel<<<64, 256>>>(E, F_w, F_b, B1_w, B2_w);
    // 3,4) input-driven terms
    uproj_kernel<<<dim3(8, 16, 32), 256>>>(u, Dv, bv, G1, NWW);
    uproj_kernel<<<dim3(8, 16, 32), 256>>>(u, B2hat, fbhat, G2, NXX);
    // 5) init flags + state
    init_kernel<<<64, 256>>>();
    // 6) sequential recurrence
    recur_kernel<<<RCTAS, RTHR, SMEM_RECUR>>>();
    // 7) epilogue
    yfinal_kernel<<<dim3(16, 32), 256>>>(u, C1_w, D11_w, D12_w, by, out);
}